// round 11
// baseline (speedup 1.0000x reference)
#include <cuda_runtime.h>

// SSIM loss, fused separable 11x11 gaussian blur + ssim map + mean reduce.
// R11 = R10 (207.6us) + phase-2 s/d split + 8 CTAs/SM:
// In the 4-field {s,d,s^2,d^2} formulation, phase 2 separates into two
// independent halves ({fs,fs2} from the s-window, {fd,fd2} from d) ->
// peak live regs drop ~48 -> ~24, so the kernel fits reg cap 32 =>
// __launch_bounds__(256,8): 64 warps/SM (100% occ), smem 8x27.6KB fits.
// Same instruction totals; pure latency-hiding win. R7's cap-36 regression
// was the unsplit 5-field phase 2 (peak ~56 live) - doesn't apply.

#define IMG      512
#define TW       32
#define TH       22
#define HALO     5
#define INW      42          // TW + 2*HALO
#define INWP     44          // padded row stride
#define INH      32          // TH + 2*HALO  (=> phase2 tasks = 32*8 = 256)
#define NT       256
#define HPLANE   (INH * TW)  // 1024 floats per blurred field

#define GX       16          // 512/32
#define GY       24          // 24*22 = 528 rows, tail masked
#define PL       96
#define NB       (GX * GY * PL)   // 36864 = 36*1024

#define SMEM_FLOATS (2 * INH * INWP + 4 * HPLANE)   // 2816 + 4096 = 6912
#define SMEM_BYTES  (SMEM_FLOATS * 4)               // 27648

__device__ float g_part[NB];
__device__ float g_part2[36];

// 1D gaussian, sigma=1.5, K=11, normalized. Constant indices fold to
// FFMA immediates (rt_SMSP=1 imm-form).
__device__ __forceinline__ constexpr float gw(int k) {
    switch (k) {
        case 0:  return 0.00102838f;
        case 1:  return 0.00759877f;
        case 2:  return 0.03600077f;
        case 3:  return 0.10936069f;
        case 4:  return 0.21300554f;
        case 5:  return 0.26601173f;
        case 6:  return 0.21300554f;
        case 7:  return 0.10936069f;
        case 8:  return 0.03600077f;
        case 9:  return 0.00759877f;
        case 10: return 0.00102838f;
    }
    return 0.0f;
}

// One half of the horizontal blur: window w16 -> {B(x), B(x^2)} for 4 cols,
// stored to planes p0 (linear) and p1 (squared). Peak live ~24 regs.
__device__ __forceinline__ void hblur_half(const float* __restrict__ src,
                                           float* __restrict__ dst0,
                                           float* __restrict__ dst1,
                                           int row, int c0) {
    float a[16];
    {
        const float4* a4 = (const float4*)(src + row * INWP + c0);
        ((float4*)a)[0] = a4[0]; ((float4*)a)[1] = a4[1];
        ((float4*)a)[2] = a4[2]; ((float4*)a)[3] = a4[3];
    }
    float f[4]  = {0.f, 0.f, 0.f, 0.f};
    float f2[4] = {0.f, 0.f, 0.f, 0.f};
    #pragma unroll
    for (int i = 0; i < 14; i++) {
        float v = a[i];
        float vv = v * v;
        #pragma unroll
        for (int j = 0; j < 4; j++) {
            int k = i - j;
            if (k >= 0 && k < 11) {
                float w = gw(k);
                f[j]  = fmaf(v,  w, f[j]);
                f2[j] = fmaf(vv, w, f2[j]);
            }
        }
    }
    float* h0 = dst0 + row * TW + c0;
    float* h1 = dst1 + row * TW + c0;
    *(float4*)h0 = make_float4(f[0],  f[1],  f[2],  f[3]);
    *(float4*)h1 = make_float4(f2[0], f2[1], f2[2], f2[3]);
}

__global__ __launch_bounds__(NT, 8)
void ssim_main(const float* __restrict__ img1, const float* __restrict__ img2) {
    extern __shared__ float smem[];
    float* ss = smem;                       // s = x1+x2 tile [INH][INWP]
    float* sd = smem + INH * INWP;          // d = x1-x2 tile
    float* sh = smem + 2 * INH * INWP;      // 4 planar fields [INH][TW]
    __shared__ float wsum[NT / 32];

    const int tid = threadIdx.x;
    const int gx0 = blockIdx.x * TW - HALO;
    const int gy0 = blockIdx.y * TH - HALO;
    const size_t pbase = (size_t)blockIdx.z * (IMG * IMG);
    const float* p1 = img1 + pbase;
    const float* p2 = img2 + pbase;

    // ---- Phase 1: global -> smem. s=(i1+i2)*0.5+1, d=(i1-i2)*0.5.
    //      Zero-pad OOB (x1=x2=0 => s=0, d=0). ----
    {
        const int r  = tid >> 3;
        const int c  = tid & 7;
        const int gy = gy0 + r;
        const bool rowok = (gy >= 0) && (gy < IMG);
        const float* q1 = p1 + (size_t)gy * IMG;
        const float* q2 = p2 + (size_t)gy * IMG;
        #pragma unroll
        for (int k = 0; k < 6; k++) {
            int cc = c + 8 * k;
            if (k < 5 || cc < INWP) {
                int gx = gx0 + cc;
                float vs = 0.f, vd = 0.f;
                if (rowok && cc < INW && gx >= 0 && gx < IMG) {
                    float a = q1[gx], b = q2[gx];
                    vs = fmaf(a + b, 0.5f, 1.0f);
                    vd = (a - b) * 0.5f;
                }
                ss[r * INWP + cc] = vs;
                sd[r * INWP + cc] = vd;
            }
        }
    }
    __syncthreads();

    // ---- Phase 2: horizontal 11-tap blur, two independent halves ----
    {
        const int row = tid >> 3;
        const int c0  = (tid & 7) << 2;
        hblur_half(ss, sh + 0 * HPLANE, sh + 2 * HPLANE, row, c0);  // s half
        hblur_half(sd, sh + 1 * HPLANE, sh + 3 * HPLANE, row, c0);  // d half
    }
    __syncthreads();

    // ---- Phase 3: vertical blur + ssim. groups 0-5: 3 rows, 6-7: 2 rows ----
    const int col = tid & 31;
    const int g   = tid >> 5;
    const int r_start = (g < 6) ? 3 * g : 18 + 2 * (g - 6);

    float acc0[3], acc1[3], acc2[3], acc3[3];
    #pragma unroll
    for (int j = 0; j < 3; j++) {
        acc0[j] = 0.f; acc1[j] = 0.f; acc2[j] = 0.f; acc3[j] = 0.f;
    }

    #pragma unroll
    for (int i = 0; i < 13; i++) {
        int ri = r_start + i;
        if (ri > INH - 1) ri = INH - 1;   // only dead lanes hit clamp
        const float* hp = sh + ri * TW + col;
        float h0 = hp[0 * HPLANE];
        float h1 = hp[1 * HPLANE];
        float h2 = hp[2 * HPLANE];
        float h3 = hp[3 * HPLANE];
        #pragma unroll
        for (int j = 0; j < 3; j++) {
            int k = i - j;
            if (k >= 0 && k < 11) {
                float w = gw(k);
                acc0[j] = fmaf(h0, w, acc0[j]);
                acc1[j] = fmaf(h1, w, acc1[j]);
                acc2[j] = fmaf(h2, w, acc2[j]);
                acc3[j] = fmaf(h3, w, acc3[j]);
            }
        }
    }

    const float C1 = 0.0001f;   // 0.01^2
    const float C2 = 0.0009f;   // 0.03^2
    const int   gyb = blockIdx.y * TH + r_start;
    float tsum = 0.f;
    #pragma unroll
    for (int j = 0; j < 3; j++) {
        bool valid = (j < 2 || g < 6) && (gyb + j < IMG);
        if (valid) {
            float Bs  = acc0[j], Bd  = acc1[j];
            float Bs2 = acc2[j], Bd2 = acc3[j];
            float bss = Bs * Bs, bdd = Bd * Bd;
            float mu12   = 0.25f * (bss - bdd);        // mu1*mu2
            float musq   = 0.50f * (bss + bdd);        // mu1^2 + mu2^2
            float sig12  = 0.25f * (Bs2 - Bd2) - mu12; // sigma12
            float sigsum = 0.50f * (Bs2 + Bd2) - musq; // sigma1^2 + sigma2^2
            float num = fmaf(2.f, mu12,  C1) * fmaf(2.f, sig12, C2);
            float den = (musq + C1) * (sigsum + C2);
            tsum += __fdividef(num, den);
        }
    }

    // ---- Reduction: warp shuffle -> static wsum (1 barrier) -> STG ----
    #pragma unroll
    for (int off = 16; off; off >>= 1)
        tsum += __shfl_xor_sync(0xffffffffu, tsum, off);

    if ((tid & 31) == 0) wsum[tid >> 5] = tsum;
    __syncthreads();
    if (tid == 0) {
        float bs = 0.f;
        #pragma unroll
        for (int i = 0; i < NT / 32; i++) bs += wsum[i];
        int slot = (blockIdx.z * GY + blockIdx.y) * GX + blockIdx.x;
        g_part[slot] = bs;
    }
}

__global__ __launch_bounds__(1024)
void ssim_reduce1() {
    __shared__ float ws[32];
    const int tid = threadIdx.x;
    float s = g_part[blockIdx.x * 1024 + tid];

    #pragma unroll
    for (int off = 16; off; off >>= 1)
        s += __shfl_xor_sync(0xffffffffu, s, off);
    if ((tid & 31) == 0) ws[tid >> 5] = s;
    __syncthreads();
    if (tid < 32) {
        float t = ws[tid];
        #pragma unroll
        for (int off = 16; off; off >>= 1)
            t += __shfl_xor_sync(0xffffffffu, t, off);
        if (tid == 0) g_part2[blockIdx.x] = t;
    }
}

__global__ void ssim_fin(float* out, double inv_n) {
    const int tid = threadIdx.x;   // 32 threads
    double s = (double)g_part2[tid];
    if (tid < 4) s += (double)g_part2[tid + 32];
    #pragma unroll
    for (int off = 16; off; off >>= 1)
        s += __shfl_xor_sync(0xffffffffu, s, off);
    if (tid == 0) out[0] = 1.0f - (float)(s * inv_n);
}

extern "C" void kernel_launch(void* const* d_in, const int* in_sizes, int n_in,
                              void* d_out, int out_size) {
    const float* img1 = (const float*)d_in[0];
    const float* img2 = (const float*)d_in[1];
    (void)n_in; (void)out_size; (void)in_sizes;

    cudaFuncSetAttribute(ssim_main, cudaFuncAttributeMaxDynamicSharedMemorySize,
                         SMEM_BYTES);

    dim3 grid(GX, GY, PL);
    ssim_main<<<grid, NT, SMEM_BYTES>>>(img1, img2);

    ssim_reduce1<<<36, 1024>>>();
    double inv_n = 1.0 / ((double)PL * IMG * IMG);
    ssim_fin<<<1, 32>>>((float*)d_out, inv_n);
}